// round 12
// baseline (speedup 1.0000x reference)
#include <cuda_runtime.h>
#include <cstdint>

#define NN 8192u
#define MD 8193u
#define MM 67125249u            // 8193*8193
#define BIAS_START 67117056u    // 8192*8193 (bias row start within matrix)
#define DIAG_STRIDE 8194u
#define CLCU 16384u
#define AL_START 16384u         // float offset of A_l
#define AU_START 67141633u      // AL_START + MM
#define CORNER_OFF 67125248u    // within-matrix corner offset (8192*8194)
#define DIAG_MID 4097u          // diag [0, DIAG_MID) in chunk 1, rest in chunk 2
#define SPLIT 33562628u         // within-matrix split (> diag[4096], < diag[4097])
#define EPS_ALPHA 1e-5f

// flags: bit0 = use L-side values; bit1 = write bias row + corner; bit2 = write cl/cu.

struct Relax { float cl, cu, dl, du, bl, bu; };

__device__ __forceinline__ Relax relax(float l, float u)
{
    float den_ul = (u > l)    ? (u - l)    : 1.0f;
    float den_6l = (l < 6.0f) ? (6.0f - l) : 1.0f;
    float u_safe = (u > 0.0f) ? u          : 1.0f;

    bool mA = (u > 0.0f) && (u <= 6.0f) && (l >= 0.0f);
    bool mB = (u > 0.0f) && (u <= 6.0f) && (l <  0.0f);
    bool mC = (u > 6.0f) && (l <= 0.0f);
    bool mD = (u > 6.0f) && (l >  0.0f) && (l <= 6.0f);
    bool mE = (l > 6.0f);

    float alpha_B = (u < -l) ? EPS_ALPHA : 1.0f;
    float lam_B   = u / den_ul;
    float aU_C    = ((u - 6.0f) < (6.0f - l)) ? (6.0f / den_6l) : EPS_ALPHA;
    float aL_C    = (u < -l) ? EPS_ALPHA : (6.0f / u_safe);
    float aU_D    = ((u - 6.0f) < (6.0f - l)) ? 1.0f : EPS_ALPHA;
    float aL_D    = (6.0f - l) / den_ul;

    float fA = mA ? 1.0f : 0.0f;
    float fB = mB ? 1.0f : 0.0f;
    float fC = mC ? 1.0f : 0.0f;
    float fD = mD ? 1.0f : 0.0f;
    float fE = mE ? 1.0f : 0.0f;

    Relax r;
    r.du = fA * 1.0f + fB * lam_B   + fC * aU_C + fD * aU_D;
    r.dl = fA * 1.0f + fB * alpha_B + fC * aL_C + fD * aL_D;
    r.bu = fB * (-lam_B * l)
         + fC * (6.0f * (1.0f - aU_C))
         + fD * (6.0f * (1.0f - aU_D))
         + fE * 6.0f;
    r.bl = fD * (l * (1.0f - aL_D)) + fE * 6.0f;
    r.cu = fA * u + fB * u
         + fC * (6.0f + aU_C * (u - 6.0f))
         + fD * (6.0f + aU_D * (u - 6.0f))
         + fE * 6.0f;
    r.cl = fA * l + fB * (alpha_B * l) + fC * (aL_C * l)
         + fD * l + fE * 6.0f;
    return r;
}

__global__ void relu6_fill_piece(const float* __restrict__ lower,
                                 const float* __restrict__ upper,
                                 float* __restrict__ out,
                                 unsigned base, unsigned diagLo, unsigned diagHi,
                                 unsigned flags)
{
    unsigned t = blockIdx.x * blockDim.x + threadIdx.x;
    bool isL = (flags & 1u) != 0u;
    unsigned nclcu = (flags & 4u) ? CLCU : 0u;

    if (t < nclcu) {
        unsigned i = t & (NN - 1u);
        Relax r = relax(lower[i], upper[i]);
        out[t] = (t < NN) ? r.cl : r.cu;
        return;
    }
    unsigned t2 = t - nclcu;
    unsigned ndiag = diagHi - diagLo;
    if (t2 < ndiag) {
        unsigned i = diagLo + t2;
        Relax r = relax(lower[i], upper[i]);
        out[base + i * DIAG_STRIDE] = isL ? r.dl : r.du;
        return;
    }
    if ((flags & 2u) == 0u) return;
    unsigned t3 = t2 - ndiag;
    if (t3 < NN) {
        Relax r = relax(lower[t3], upper[t3]);
        out[base + BIAS_START + t3] = isL ? r.bl : r.bu;
        return;
    }
    if (t3 == NN) out[base + CORNER_OFF] = 1.0f;
}

extern "C" void kernel_launch(void* const* d_in, const int* in_sizes, int n_in,
                              void* d_out, int out_size)
{
    const float* lower = (const float*)d_in[0];
    const float* upper = (const float*)d_in[1];
    float* out = (float*)d_out;

    // Lazy one-time creation (first call = correctness run, before the
    // harness's pre-capture memory baseline and before graph capture).
    static cudaStream_t s1 = nullptr, s2 = nullptr;
    static cudaEvent_t e0 = nullptr, m1 = nullptr, m2 = nullptr,
                       m3 = nullptr, m4 = nullptr, eA = nullptr, eB = nullptr;
    if (s1 == nullptr) {
        cudaStreamCreateWithFlags(&s1, cudaStreamNonBlocking);
        cudaStreamCreateWithFlags(&s2, cudaStreamNonBlocking);
        cudaEventCreateWithFlags(&e0, cudaEventDisableTiming);
        cudaEventCreateWithFlags(&m1, cudaEventDisableTiming);
        cudaEventCreateWithFlags(&m2, cudaEventDisableTiming);
        cudaEventCreateWithFlags(&m3, cudaEventDisableTiming);
        cudaEventCreateWithFlags(&m4, cudaEventDisableTiming);
        cudaEventCreateWithFlags(&eA, cudaEventDisableTiming);
        cudaEventCreateWithFlags(&eB, cudaEventDisableTiming);
    }

    // Fork from the capture (legacy) stream.
    cudaEventRecord(e0, 0);
    cudaStreamWaitEvent(s1, e0, 0);
    cudaStreamWaitEvent(s2, e0, 0);

    const size_t F = sizeof(float);
    // s1: four 1D memset chunks covering all matrix bytes (fast CE path).
    cudaMemsetAsync(out + AL_START,         0, (size_t)SPLIT * F,        s1);
    cudaEventRecord(m1, s1);
    cudaMemsetAsync(out + AL_START + SPLIT, 0, (size_t)(MM - SPLIT) * F, s1);
    cudaEventRecord(m2, s1);
    cudaMemsetAsync(out + AU_START,         0, (size_t)SPLIT * F,        s1);
    cudaEventRecord(m3, s1);
    cudaMemsetAsync(out + AU_START + SPLIT, 0, (size_t)(MM - SPLIT) * F, s1);
    cudaEventRecord(m4, s1);

    // s2: fill pieces gated on their chunk's memset, overlapped with the rest.
    // piece0: cl/cu + A_l diag [0, DIAG_MID)            flags = L | CLCU
    cudaStreamWaitEvent(s2, m1, 0);
    relu6_fill_piece<<<(CLCU + DIAG_MID + 255u) / 256u, 256, 0, s2>>>(
        lower, upper, out, AL_START, 0u, DIAG_MID, 1u | 4u);
    // piece1: A_l diag [DIAG_MID, NN) + bias + corner   flags = L | BIAS
    cudaStreamWaitEvent(s2, m2, 0);
    relu6_fill_piece<<<((NN - DIAG_MID) + NN + 1u + 255u) / 256u, 256, 0, s2>>>(
        lower, upper, out, AL_START, DIAG_MID, NN, 1u | 2u);
    // piece2: A_u diag [0, DIAG_MID)                    flags = 0 (U side)
    cudaStreamWaitEvent(s2, m3, 0);
    relu6_fill_piece<<<(DIAG_MID + 255u) / 256u, 256, 0, s2>>>(
        lower, upper, out, AU_START, 0u, DIAG_MID, 0u);
    // piece3: A_u diag [DIAG_MID, NN) + bias + corner   flags = BIAS
    cudaStreamWaitEvent(s2, m4, 0);
    relu6_fill_piece<<<((NN - DIAG_MID) + NN + 1u + 255u) / 256u, 256, 0, s2>>>(
        lower, upper, out, AU_START, DIAG_MID, NN, 2u);

    // Join back to the capture stream.
    cudaEventRecord(eA, s1);
    cudaEventRecord(eB, s2);
    cudaStreamWaitEvent(0, eA, 0);
    cudaStreamWaitEvent(0, eB, 0);
}